// round 12
// baseline (speedup 1.0000x reference)
#include <cuda_runtime.h>
#include <cstdint>

// Problem constants (from reference setup_inputs)
#define PB 16
#define PL 4096
#define PD 768
#define PS 128
#define D4 (PD / 4)          // 192 float4 per row
#define THREADS D4           // one float4 column per thread
#define NWARPS (THREADS / 32)
#define SEGLEN (PL / PS)     // 32 — every segment in this dataset

__device__ __forceinline__ void accum1(const float4& v, float4& a,
                                       int& cx, int& cy, int& cz, int& cw) {
    a.x += v.x; a.y += v.y; a.z += v.z; a.w += v.w;
    cx += (v.x != 0.f); cy += (v.y != 0.f);
    cz += (v.z != 0.f); cw += (v.w != 0.f);
}

// One CTA per (b, s). Hot path: compile-time trip count SEGLEN -> ptxas fully
// unrolls and software-pipelines the 32 LDG.128s. launch_bounds(192,7) gives
// a 48-reg budget (vs 40 at occ 8) so the scheduler can front-batch deeper;
// in-flight bytes = warps x MLP rises despite one fewer CTA/SM.
__global__ __launch_bounds__(THREADS, 7) void pooling_kernel(
    const float* __restrict__ wv,            // [B, L, D]
    const int* __restrict__ rep_ids,         // [B, S]
    const int* __restrict__ rep_mask,        // [B, S] bool as int32
    const int* __restrict__ lengths,         // [B, S]
    const int* __restrict__ len_mask,        // [B, S] bool as int32
    float* __restrict__ out,                 // [B, 2S, D] (+ mask tail)
    int write_mask)
{
    const int bs = blockIdx.x;
    const int b = bs >> 7;
    const int s = bs & (PS - 1);
    const int tid = threadIdx.x;
    const int lane = tid & 31;
    const int wid = tid >> 5;

    __shared__ int sred[NWARPS];

    // ---- start = sum_{j < s} lengths[b, j] (block reduction) ----
    const int* lrow = lengths + b * PS;
    int part = (tid < s) ? __ldg(&lrow[tid]) : 0;    // tid<192 covers s<=127
#pragma unroll
    for (int o = 16; o > 0; o >>= 1)
        part += __shfl_down_sync(0xffffffffu, part, o);
    if (lane == 0) sred[wid] = part;
    __syncthreads();
    int start = 0;
#pragma unroll
    for (int w = 0; w < NWARPS; w++) start += sred[w];

    int len = __ldg(&lengths[bs]);
    int end = start + len;
    if (start > PL) start = PL;
    if (end > PL) end = PL;
    const int n = end - start;

    const float4* __restrict__ wvb =
        reinterpret_cast<const float4*>(wv) + (unsigned)b * (PL * D4);

    // ---- early gather load (independent of stream; overlaps latency) ----
    int id = __ldg(&rep_ids[bs]);
    if (id < 0) id = 0;
    if (id >= PL) id = PL - 1;
    float4 g = __ldg(&wvb[(unsigned)id * D4 + tid]);

    // ---- streamed segment sum + per-feature nonzero counts ----
    const float4* __restrict__ p = wvb + (unsigned)start * D4 + tid;

    float4 acc = make_float4(0.f, 0.f, 0.f, 0.f);
    int cx = 0, cy = 0, cz = 0, cw = 0;

    if (n == SEGLEN) {
        // Compile-time trip count: full unroll, ptxas schedules the batching.
#pragma unroll
        for (int t = 0; t < SEGLEN; t++) {
            float4 v = __ldcs(p + t * D4);
            accum1(v, acc, cx, cy, cz, cw);
        }
    } else {
        // Generic path (any segment lengths), unrolled by 4.
        int t = 0;
        for (; t + 4 <= n; t += 4) {
            float4 v0 = __ldcs(p + (t + 0) * D4);
            float4 v1 = __ldcs(p + (t + 1) * D4);
            float4 v2 = __ldcs(p + (t + 2) * D4);
            float4 v3 = __ldcs(p + (t + 3) * D4);
            accum1(v0, acc, cx, cy, cz, cw);
            accum1(v1, acc, cx, cy, cz, cw);
            accum1(v2, acc, cx, cy, cz, cw);
            accum1(v3, acc, cx, cy, cz, cw);
        }
        for (; t < n; t++) {
            float4 v = __ldcs(p + t * D4);
            accum1(v, acc, cx, cy, cz, cw);
        }
    }

    // ---- block-reduce total nonzero count ----
    int nz = cx + cy + cz + cw;
#pragma unroll
    for (int o = 16; o > 0; o >>= 1)
        nz += __shfl_down_sync(0xffffffffu, nz, o);
    __syncthreads();                // sred reuse
    if (lane == 0) sred[wid] = nz;
    __syncthreads();
    int total_nz = 0;
#pragma unroll
    for (int w = 0; w < NWARPS; w++) total_nz += sred[w];

    const float mlen = len_mask[bs] ? 1.f : 0.f;
    const float mrep = rep_mask[bs] ? 1.f : 0.f;

    float4 mv;
    if (total_nz == 0) {
        mv = __ldg(&reinterpret_cast<const float4*>(wv)[tid]);  // wv[0,0,:]
    } else {
        mv.x = acc.x / (float)(cx ? cx : 1);
        mv.y = acc.y / (float)(cy ? cy : 1);
        mv.z = acc.z / (float)(cz ? cz : 1);
        mv.w = acc.w / (float)(cw ? cw : 1);
    }
    mv.x *= mlen; mv.y *= mlen; mv.z *= mlen; mv.w *= mlen;

    float4* __restrict__ outb =
        reinterpret_cast<float4*>(out) + (unsigned)b * (2 * PS * D4);
    __stcs(&outb[(unsigned)(PS + s) * D4 + tid], mv);           // mean row

    g.x *= mrep; g.y *= mrep; g.z *= mrep; g.w *= mrep;
    __stcs(&outb[(unsigned)s * D4 + tid], g);                   // rep row

    if (write_mask && tid == 0) {
        float* mo = out + (size_t)PB * 2 * PS * PD;
        mo[b * 2 * PS + s] = mrep;
        mo[b * 2 * PS + PS + s] = mlen;
    }
}

extern "C" void kernel_launch(void* const* d_in, const int* in_sizes, int n_in,
                              void* d_out, int out_size) {
    const float* wv = (const float*)d_in[0];
    const int* rep_ids = (const int*)d_in[1];
    const int* rep_mask = (const int*)d_in[2];
    const int* lengths = (const int*)d_in[3];
    const int* len_mask = (const int*)d_in[4];
    float* out = (float*)d_out;

    const int vec_elems = PB * 2 * PS * PD;
    const int write_mask = (out_size > vec_elems) ? 1 : 0;

    pooling_kernel<<<PB * PS, THREADS>>>(wv, rep_ids, rep_mask, lengths,
                                         len_mask, out, write_mask);
}

// round 13
// speedup vs baseline: 1.0009x; 1.0009x over previous
#include <cuda_runtime.h>
#include <cstdint>

// Problem constants (from reference setup_inputs)
#define PB 16
#define PL 4096
#define PD 768
#define PS 128
#define D4 (PD / 4)          // 192 float4 per row
#define THREADS D4           // one float4 column per thread
#define NWARPS (THREADS / 32)
#define SEGLEN (PL / PS)     // 32 — every segment in this dataset

__device__ __forceinline__ void accum1(const float4& v, float4& a,
                                       int& cx, int& cy, int& cz, int& cw) {
    a.x += v.x; a.y += v.y; a.z += v.z; a.w += v.w;
    cx += (v.x != 0.f); cy += (v.y != 0.f);
    cz += (v.z != 0.f); cw += (v.w != 0.f);
}

// FINAL (best measured: 34.2us kernel, 6.06 TB/s = ~96% of LTS-path ceiling).
// One CTA per (b, s). Hot path: compile-time trip count SEGLEN -> ptxas fully
// unrolls and software-pipelines the 32 LDG.128s under the occ-8 register cap
// (40 regs). Evict-first loads/stores keep L2 for metadata + gather reuse.
// Gather row issued in the prologue to overlap its latency with the stream.
// Generic runtime-length fallback kept for correctness on arbitrary lengths.
__global__ __launch_bounds__(THREADS, 8) void pooling_kernel(
    const float* __restrict__ wv,            // [B, L, D]
    const int* __restrict__ rep_ids,         // [B, S]
    const int* __restrict__ rep_mask,        // [B, S] bool as int32
    const int* __restrict__ lengths,         // [B, S]
    const int* __restrict__ len_mask,        // [B, S] bool as int32
    float* __restrict__ out,                 // [B, 2S, D] (+ mask tail)
    int write_mask)
{
    const int bs = blockIdx.x;
    const int b = bs >> 7;
    const int s = bs & (PS - 1);
    const int tid = threadIdx.x;
    const int lane = tid & 31;
    const int wid = tid >> 5;

    __shared__ int sred[NWARPS];

    // ---- start = sum_{j < s} lengths[b, j] (block reduction) ----
    const int* lrow = lengths + b * PS;
    int part = (tid < s) ? __ldg(&lrow[tid]) : 0;    // tid<192 covers s<=127
#pragma unroll
    for (int o = 16; o > 0; o >>= 1)
        part += __shfl_down_sync(0xffffffffu, part, o);
    if (lane == 0) sred[wid] = part;
    __syncthreads();
    int start = 0;
#pragma unroll
    for (int w = 0; w < NWARPS; w++) start += sred[w];

    int len = __ldg(&lengths[bs]);
    int end = start + len;
    if (start > PL) start = PL;
    if (end > PL) end = PL;
    const int n = end - start;

    const float4* __restrict__ wvb =
        reinterpret_cast<const float4*>(wv) + (unsigned)b * (PL * D4);

    // ---- early gather load (independent of stream; overlaps latency) ----
    int id = __ldg(&rep_ids[bs]);
    if (id < 0) id = 0;
    if (id >= PL) id = PL - 1;
    float4 g = __ldg(&wvb[(unsigned)id * D4 + tid]);

    // ---- streamed segment sum + per-feature nonzero counts ----
    const float4* __restrict__ p = wvb + (unsigned)start * D4 + tid;

    float4 acc = make_float4(0.f, 0.f, 0.f, 0.f);
    int cx = 0, cy = 0, cz = 0, cw = 0;

    if (n == SEGLEN) {
        // Compile-time trip count: full unroll, ptxas schedules the batching.
#pragma unroll
        for (int t = 0; t < SEGLEN; t++) {
            float4 v = __ldcs(p + t * D4);
            accum1(v, acc, cx, cy, cz, cw);
        }
    } else {
        // Generic path (any segment lengths), unrolled by 4.
        int t = 0;
        for (; t + 4 <= n; t += 4) {
            float4 v0 = __ldcs(p + (t + 0) * D4);
            float4 v1 = __ldcs(p + (t + 1) * D4);
            float4 v2 = __ldcs(p + (t + 2) * D4);
            float4 v3 = __ldcs(p + (t + 3) * D4);
            accum1(v0, acc, cx, cy, cz, cw);
            accum1(v1, acc, cx, cy, cz, cw);
            accum1(v2, acc, cx, cy, cz, cw);
            accum1(v3, acc, cx, cy, cz, cw);
        }
        for (; t < n; t++) {
            float4 v = __ldcs(p + t * D4);
            accum1(v, acc, cx, cy, cz, cw);
        }
    }

    // ---- block-reduce total nonzero count ----
    int nz = cx + cy + cz + cw;
#pragma unroll
    for (int o = 16; o > 0; o >>= 1)
        nz += __shfl_down_sync(0xffffffffu, nz, o);
    __syncthreads();                // sred reuse
    if (lane == 0) sred[wid] = nz;
    __syncthreads();
    int total_nz = 0;
#pragma unroll
    for (int w = 0; w < NWARPS; w++) total_nz += sred[w];

    const float mlen = len_mask[bs] ? 1.f : 0.f;
    const float mrep = rep_mask[bs] ? 1.f : 0.f;

    float4 mv;
    if (total_nz == 0) {
        mv = __ldg(&reinterpret_cast<const float4*>(wv)[tid]);  // wv[0,0,:]
    } else {
        mv.x = acc.x / (float)(cx ? cx : 1);
        mv.y = acc.y / (float)(cy ? cy : 1);
        mv.z = acc.z / (float)(cz ? cz : 1);
        mv.w = acc.w / (float)(cw ? cw : 1);
    }
    mv.x *= mlen; mv.y *= mlen; mv.z *= mlen; mv.w *= mlen;

    float4* __restrict__ outb =
        reinterpret_cast<float4*>(out) + (unsigned)b * (2 * PS * D4);
    __stcs(&outb[(unsigned)(PS + s) * D4 + tid], mv);           // mean row

    g.x *= mrep; g.y *= mrep; g.z *= mrep; g.w *= mrep;
    __stcs(&outb[(unsigned)s * D4 + tid], g);                   // rep row

    if (write_mask && tid == 0) {
        float* mo = out + (size_t)PB * 2 * PS * PD;
        mo[b * 2 * PS + s] = mrep;
        mo[b * 2 * PS + PS + s] = mlen;
    }
}

extern "C" void kernel_launch(void* const* d_in, const int* in_sizes, int n_in,
                              void* d_out, int out_size) {
    const float* wv = (const float*)d_in[0];
    const int* rep_ids = (const int*)d_in[1];
    const int* rep_mask = (const int*)d_in[2];
    const int* lengths = (const int*)d_in[3];
    const int* len_mask = (const int*)d_in[4];
    float* out = (float*)d_out;

    const int vec_elems = PB * 2 * PS * PD;
    const int write_mask = (out_size > vec_elems) ? 1 : 0;

    pooling_kernel<<<PB * PS, THREADS>>>(wv, rep_ids, rep_mask, lengths,
                                         len_mask, out, write_mask);
}